// round 5
// baseline (speedup 1.0000x reference)
#include <cuda_runtime.h>
#include <math.h>
#include <stdint.h>

// ===========================================================================
// StreamingSSMCell (B=8192, D=1024, DCONV=4) — packed fp32 (fma.rn.f32x2) GEMM
//   Legacy mma.sync tf32 measured ~27 TF/s on sm_103 regardless of frontend
//   (backend ceiling); tcgen05 unavailable (compute_103 target). FFMA2 doubles
//   the fp32 SIMT rate instead, with full fp32 precision.
//   d_out layout: [ out (B*D) | h_new (B*D) | new_buf (B*D*4) ]
// ===========================================================================

#define D_MODEL 1024
#define TWO_D   2048
#define BATCH   8192

__device__ float g_xz[(size_t)BATCH * TWO_D];
__device__ float g_g [(size_t)BATCH * D_MODEL];

// ------------------------------ GEMM config --------------------------------
#define BM 128
#define BN 128
#define BK 16
#define ASTR 132                 // padded words per k-row (2-way STS conflicts max)
#define NTHREADS 256

typedef unsigned long long u64;

#define FMA2(c, a, b) \
    asm("fma.rn.f32x2 %0, %1, %2, %0;" : "+l"(c) : "l"(a), "l"(b))

#define PACK2(d, lo, hi) \
    asm("mov.b64 %0, {%1, %2};" : "=l"(d) : "r"(lo), "r"(hi))

#define UNPACK2(lo, hi, s) \
    asm("mov.b64 {%0, %1}, %2;" : "=r"(lo), "=r"(hi) : "l"(s))

// ------------------------- packed-fp32 GEMM --------------------------------
// C[m,n] = sum_k A[m,k]*Bm[n,k] + bias[n]; A [M,K] lda, Bm [N,K] ldb (K-major)
// grid = (N/128, M/128), 256 threads, 8x8 per thread, acc packed over M pairs.
__global__ __launch_bounds__(NTHREADS, 2)
void gemm_f32x2(const float* __restrict__ A, int lda,
                const float* __restrict__ Bm, int ldb,
                const float* __restrict__ bias,
                float* __restrict__ C, int ldc, int K)
{
    __shared__ float As[2][BK][ASTR];
    __shared__ float Bs[2][BK][ASTR];

    const int tid = threadIdx.x;
    const int tx = tid & 15;            // n-tile: 8 cols at tx*8
    const int ty = tid >> 4;            // m-tile: 8 rows at ty*8
    const int m0 = blockIdx.y * BM;
    const int n0 = blockIdx.x * BN;

    // global load mapping: chunk id = tid + q*256 -> row = id>>2, kc = id&3
    const int r0 = tid >> 2;            // 0..63
    const int kc = tid & 3;             // float4 chunk within BK=16
    const float* gA0 = A  + (size_t)(m0 + r0)      * lda + kc * 4;
    const float* gA1 = A  + (size_t)(m0 + r0 + 64) * lda + kc * 4;
    const float* gB0 = Bm + (size_t)(n0 + r0)      * ldb + kc * 4;
    const float* gB1 = Bm + (size_t)(n0 + r0 + 64) * ldb + kc * 4;

    u64 acc[4][8];
    #pragma unroll
    for (int i = 0; i < 4; i++)
        #pragma unroll
        for (int j = 0; j < 8; j++) acc[i][j] = 0ULL;   // (0.0f, 0.0f)

    const int T = K / BK;

    float4 ra0, ra1, rb0, rb1;

    // prologue: load + store stage 0
    ra0 = *(const float4*)(gA0);
    ra1 = *(const float4*)(gA1);
    rb0 = *(const float4*)(gB0);
    rb1 = *(const float4*)(gB1);
    {
        #pragma unroll
        for (int j = 0; j < 4; j++) {
            As[0][kc * 4 + j][r0]      = ((const float*)&ra0)[j];
            As[0][kc * 4 + j][r0 + 64] = ((const float*)&ra1)[j];
            Bs[0][kc * 4 + j][r0]      = ((const float*)&rb0)[j];
            Bs[0][kc * 4 + j][r0 + 64] = ((const float*)&rb1)[j];
        }
    }
    __syncthreads();

    for (int t = 0; t < T; t++) {
        const int buf = t & 1;

        if (t + 1 < T) {
            const size_t off = (size_t)(t + 1) * BK;
            ra0 = *(const float4*)(gA0 + off);
            ra1 = *(const float4*)(gA1 + off);
            rb0 = *(const float4*)(gB0 + off);
            rb1 = *(const float4*)(gB1 + off);
        }

        #pragma unroll
        for (int k = 0; k < BK; k++) {
            // A pairs load directly as packed 64-bit lanes (m, m+1)
            const u64* ap = (const u64*)&As[buf][k][ty * 8];
            u64 a2[4];
            a2[0] = ap[0]; a2[1] = ap[1]; a2[2] = ap[2]; a2[3] = ap[3];

            float4 b0 = *(const float4*)&Bs[buf][k][tx * 8];
            float4 b1 = *(const float4*)&Bs[buf][k][tx * 8 + 4];
            u64 bd[8];
            PACK2(bd[0], __float_as_uint(b0.x), __float_as_uint(b0.x));
            PACK2(bd[1], __float_as_uint(b0.y), __float_as_uint(b0.y));
            PACK2(bd[2], __float_as_uint(b0.z), __float_as_uint(b0.z));
            PACK2(bd[3], __float_as_uint(b0.w), __float_as_uint(b0.w));
            PACK2(bd[4], __float_as_uint(b1.x), __float_as_uint(b1.x));
            PACK2(bd[5], __float_as_uint(b1.y), __float_as_uint(b1.y));
            PACK2(bd[6], __float_as_uint(b1.z), __float_as_uint(b1.z));
            PACK2(bd[7], __float_as_uint(b1.w), __float_as_uint(b1.w));

            #pragma unroll
            for (int i = 0; i < 4; i++)
                #pragma unroll
                for (int j = 0; j < 8; j++)
                    FMA2(acc[i][j], a2[i], bd[j]);
        }

        if (t + 1 < T) {
            const int nb = (t + 1) & 1;
            #pragma unroll
            for (int j = 0; j < 4; j++) {
                As[nb][kc * 4 + j][r0]      = ((const float*)&ra0)[j];
                As[nb][kc * 4 + j][r0 + 64] = ((const float*)&ra1)[j];
                Bs[nb][kc * 4 + j][r0]      = ((const float*)&rb0)[j];
                Bs[nb][kc * 4 + j][r0 + 64] = ((const float*)&rb1)[j];
            }
            __syncthreads();
        }
    }

    // epilogue: unpack, add bias, store
    const float4 bb0 = *(const float4*)(bias + n0 + tx * 8);
    const float4 bb1 = *(const float4*)(bias + n0 + tx * 8 + 4);

    #pragma unroll
    for (int i = 0; i < 4; i++) {
        float lo[8], hi[8];
        #pragma unroll
        for (int j = 0; j < 8; j++) {
            uint32_t l, hgh;
            UNPACK2(l, hgh, acc[i][j]);
            lo[j] = __uint_as_float(l);
            hi[j] = __uint_as_float(hgh);
        }
        const int m = m0 + ty * 8 + i * 2;
        float* c0 = C + (size_t)m * ldc + n0 + tx * 8;
        float* c1 = c0 + ldc;
        float4 v;
        v.x = lo[0] + bb0.x; v.y = lo[1] + bb0.y; v.z = lo[2] + bb0.z; v.w = lo[3] + bb0.w;
        *(float4*)(c0) = v;
        v.x = lo[4] + bb1.x; v.y = lo[5] + bb1.y; v.z = lo[6] + bb1.z; v.w = lo[7] + bb1.w;
        *(float4*)(c0 + 4) = v;
        v.x = hi[0] + bb0.x; v.y = hi[1] + bb0.y; v.z = hi[2] + bb0.z; v.w = hi[3] + bb0.w;
        *(float4*)(c1) = v;
        v.x = hi[4] + bb1.x; v.y = hi[5] + bb1.y; v.z = hi[6] + bb1.z; v.w = hi[7] + bb1.w;
        *(float4*)(c1 + 4) = v;
    }
}

// ------------------------ fused elementwise stage ---------------------------
__device__ __forceinline__ float silu_f(float x) { return x / (1.0f + expf(-x)); }

__global__ void fused_elementwise(const float* __restrict__ xz,
                                  const float* __restrict__ h,
                                  const float* __restrict__ conv_buf,
                                  const float* __restrict__ conv_w,
                                  const float* __restrict__ conv_b,
                                  float* __restrict__ out_hnew,
                                  float* __restrict__ out_newbuf,
                                  float* __restrict__ g_out,
                                  int B, int D)
{
    const int idx = blockIdx.x * blockDim.x + threadIdx.x;
    if (idx >= B * D) return;
    const int b = idx / D;
    const int d = idx - b * D;

    const float xi = xz[(size_t)b * 2 * D + d];
    const float z  = xz[(size_t)b * 2 * D + D + d];

    const float4 cb = *(const float4*)(conv_buf + (size_t)idx * 4);
    const float4 cw = *(const float4*)(conv_w + (size_t)d * 4);

    float co = cb.y * cw.x + cb.z * cw.y + cb.w * cw.z + xi * cw.w + conv_b[d];
    co = silu_f(co);

    const float lmin = 2.302585092994046f;   // log(10)
    const float lmax = 7.600902459542082f;   // log(2000)
    const float t = lmin + (float)d * (lmax - lmin) / (float)(D - 1);
    const float dec = expf(-expf(-t));

    const float hn = dec * h[idx] + (1.0f - dec) * co;

    out_hnew[idx] = hn;
    float4 nb; nb.x = cb.y; nb.y = cb.z; nb.z = cb.w; nb.w = xi;
    *(float4*)(out_newbuf + (size_t)idx * 4) = nb;

    g_out[idx] = hn * silu_f(z);
}

// ------------------------------- launch ------------------------------------
extern "C" void kernel_launch(void* const* d_in, const int* in_sizes, int n_in,
                              void* d_out, int out_size)
{
    const float* x        = (const float*)d_in[0];
    const float* h        = (const float*)d_in[1];
    const float* conv_buf = (const float*)d_in[2];
    const float* W_in     = (const float*)d_in[3];
    const float* b_in     = (const float*)d_in[4];
    const float* conv_w   = (const float*)d_in[5];
    const float* conv_b   = (const float*)d_in[6];
    const float* W_out    = (const float*)d_in[7];
    const float* b_out    = (const float*)d_in[8];

    const int D = in_sizes[6];
    const int B = in_sizes[0] / D;
    const int twoD = in_sizes[4];

    float* out      = (float*)d_out;
    float* out_hnew = out + (size_t)B * D;
    float* out_nbuf = out + (size_t)2 * B * D;

    float* xz = g_xz;
    float* gg = g_g;

    // GEMM1: xz = x @ W_in^T + b_in   [B, 2D]
    {
        dim3 grid(twoD / BN, B / BM);
        gemm_f32x2<<<grid, NTHREADS>>>(x, D, W_in, D, b_in, xz, twoD, D);
    }

    // fused elementwise
    {
        const int n = B * D;
        fused_elementwise<<<(n + 255) / 256, 256>>>(
            xz, h, conv_buf, conv_w, conv_b, out_hnew, out_nbuf, gg, B, D);
    }

    // GEMM2: out = g @ W_out^T + b_out  [B, D]
    {
        dim3 grid(D / BN, B / BM);
        gemm_f32x2<<<grid, NTHREADS>>>(gg, D, W_out, D, b_out, out, D, D);
    }
}